// round 1
// baseline (speedup 1.0000x reference)
#include <cuda_runtime.h>

// GHM-C loss, two-pass:
//   pass 1: global histogram of g over 10 bins + valid count
//   small:  per-bin weights
//   pass 2: weighted pos/neg log-loss sums (double-atomic combine)
//   small:  finalize scalar
//
// Shapes fixed by problem: B=32, H=W=512 -> HW = 262144 (power of two).

static const int kHW  = 262144;
static const int kHW3 = 3 * 262144;

__device__ int    g_counts[10];
__device__ int    g_tot;
__device__ double g_sums[3];   // pos_loss, neg_loss, num_pos
__device__ float  g_w[10];

__global__ void ghm_init() {
    int t = threadIdx.x;
    if (t < 10) g_counts[t] = 0;
    if (t == 10) g_tot = 0;
    if (t < 3) g_sums[t] = 0.0;
}

__device__ __forceinline__ int bin_idx(float ga) {
    // floor(g*10) clamped to 9; matches searchsorted(edges,right)-1 except
    // within 1 ulp of an edge (negligible for this loss).
    int idx = (int)(ga * 10.0f);
    return idx > 9 ? 9 : idx;
}

__global__ void __launch_bounds__(256)
ghm_hist(const float* __restrict__ pred, const float* __restrict__ target, int nvec) {
    __shared__ int s_counts[11];
    int tid = threadIdx.x;
    if (tid < 11) s_counts[tid] = 0;
    __syncthreads();

    // per-thread byte-packed bin counters: c0 = bins0-3, c1 = bins4-7, c2 = bins8-9
    unsigned c0 = 0, c1 = 0, c2 = 0;
    int ctot = 0;
    const float EDGE_TOP = 1.0f + 1e-6f;

    int stride = gridDim.x * blockDim.x;
    for (int v = blockIdx.x * blockDim.x + tid; v < nvec; v += stride) {
        int i = v << 2;
        int b = i / kHW;            // power-of-two -> shift
        int j = i - b * kHW;
        float4 p  = *(const float4*)(pred + i);
        int tb = b * kHW3 + j;
        float4 va = *(const float4*)(target + tb + kHW);
        float4 po = *(const float4*)(target + tb + 2 * kHW);
        const float* pp = (const float*)&p;
        const float* vv = (const float*)&va;
        const float* ss = (const float*)&po;
#pragma unroll
        for (int k = 0; k < 4; k++) {
            float t  = fmaf(pp[k], vv[k], -ss[k]);
            float ga = fabsf(t);
            bool validb = vv[k] > 0.0f;
            bool pin = validb && (ga < EDGE_TOP);
            ctot += validb ? 1 : 0;
            int idx = bin_idx(ga);
            unsigned inc = pin ? (1u << ((idx & 3) * 8)) : 0u;
            if (idx < 4)      c0 += inc;
            else if (idx < 8) c1 += inc;
            else              c2 += inc;
        }
    }

    // widen bytes to 16-bit fields so a 32-lane sum can't overflow (max 28*32=896)
    unsigned e0 = c0 & 0x00FF00FFu;
    unsigned e1 = (c0 >> 8) & 0x00FF00FFu;
    unsigned e2 = c1 & 0x00FF00FFu;
    unsigned e3 = (c1 >> 8) & 0x00FF00FFu;
    unsigned e4 = (c2 & 0xFFu) | ((c2 & 0xFF00u) << 8);
#pragma unroll
    for (int o = 16; o > 0; o >>= 1) {
        e0   += __shfl_down_sync(0xffffffffu, e0, o);
        e1   += __shfl_down_sync(0xffffffffu, e1, o);
        e2   += __shfl_down_sync(0xffffffffu, e2, o);
        e3   += __shfl_down_sync(0xffffffffu, e3, o);
        e4   += __shfl_down_sync(0xffffffffu, e4, o);
        ctot += __shfl_down_sync(0xffffffffu, ctot, o);
    }
    if ((tid & 31) == 0) {
        atomicAdd(&s_counts[0], (int)(e0 & 0xFFFFu));
        atomicAdd(&s_counts[1], (int)(e1 & 0xFFFFu));
        atomicAdd(&s_counts[2], (int)(e0 >> 16));
        atomicAdd(&s_counts[3], (int)(e1 >> 16));
        atomicAdd(&s_counts[4], (int)(e2 & 0xFFFFu));
        atomicAdd(&s_counts[5], (int)(e3 & 0xFFFFu));
        atomicAdd(&s_counts[6], (int)(e2 >> 16));
        atomicAdd(&s_counts[7], (int)(e3 >> 16));
        atomicAdd(&s_counts[8], (int)(e4 & 0xFFFFu));
        atomicAdd(&s_counts[9], (int)(e4 >> 16));
        atomicAdd(&s_counts[10], ctot);
    }
    __syncthreads();
    if (tid < 10) atomicAdd(&g_counts[tid], s_counts[tid]);
    if (tid == 10) atomicAdd(&g_tot, s_counts[10]);
}

__global__ void ghm_weights() {
    if (threadIdx.x == 0) {
        float totf = fmaxf((float)g_tot, 1.0f);
        int nn = 0;
#pragma unroll
        for (int k = 0; k < 10; k++) nn += (g_counts[k] > 0) ? 1 : 0;
        float nnf = fmaxf((float)nn, 1.0f);
#pragma unroll
        for (int k = 0; k < 10; k++) {
            int c = g_counts[k];
            g_w[k] = (c > 0) ? (totf / fmaxf((float)c, 1.0f)) / nnf : 0.0f;
        }
    }
}

__global__ void __launch_bounds__(256)
ghm_loss(const float* __restrict__ pred, const float* __restrict__ target, int nvec) {
    __shared__ float s_w[10];
    __shared__ float s_red[3][8];
    int tid = threadIdx.x;
    if (tid < 10) s_w[tid] = g_w[tid];
    __syncthreads();

    const float EDGE_TOP = 1.0f + 1e-6f;
    float accP = 0.0f, accN = 0.0f, accPos = 0.0f;

    int stride = gridDim.x * blockDim.x;
    for (int v = blockIdx.x * blockDim.x + tid; v < nvec; v += stride) {
        int i = v << 2;
        int b = i / kHW;
        int j = i - b * kHW;
        float4 p  = *(const float4*)(pred + i);
        int tb = b * kHW3 + j;
        float4 hm = *(const float4*)(target + tb);
        float4 va = *(const float4*)(target + tb + kHW);
        float4 po = *(const float4*)(target + tb + 2 * kHW);
        const float* pp = (const float*)&p;
        const float* hh = (const float*)&hm;
        const float* vv = (const float*)&va;
        const float* ss = (const float*)&po;
#pragma unroll
        for (int k = 0; k < 4; k++) {
            float pv = pp[k], hv = hh[k], v1 = vv[k], sv = ss[k];
            float t  = fmaf(pv, v1, -sv);
            float ga = fabsf(t);
            bool pin = (v1 > 0.0f) && (ga < EDGE_TOP);
            int idx = bin_idx(ga);
            float w = pin ? s_w[idx] : 0.0f;
            accPos += sv;
            float posw = sv * w;
            if (posw != 0.0f) accP = fmaf(__logf(pv), posw, accP);
            float omh = 1.0f - hv;
            float nw = omh * omh; nw *= nw;
            float negw = (v1 - sv) * nw * w;
            if (negw != 0.0f) accN = fmaf(__logf(1.0f - pv), negw, accN);
        }
    }

#pragma unroll
    for (int o = 16; o > 0; o >>= 1) {
        accP   += __shfl_down_sync(0xffffffffu, accP, o);
        accN   += __shfl_down_sync(0xffffffffu, accN, o);
        accPos += __shfl_down_sync(0xffffffffu, accPos, o);
    }
    int wid = tid >> 5;
    if ((tid & 31) == 0) {
        s_red[0][wid] = accP;
        s_red[1][wid] = accN;
        s_red[2][wid] = accPos;
    }
    __syncthreads();
    if (tid == 0) {
        float a = 0.0f, bn = 0.0f, c = 0.0f;
#pragma unroll
        for (int k = 0; k < 8; k++) { a += s_red[0][k]; bn += s_red[1][k]; c += s_red[2][k]; }
        atomicAdd(&g_sums[0], (double)a);
        atomicAdd(&g_sums[1], (double)bn);
        atomicAdd(&g_sums[2], (double)c);
    }
}

__global__ void ghm_final(float* out) {
    if (threadIdx.x == 0) {
        float totf = fmaxf((float)g_tot, 1.0f);
        double ps = g_sums[0], ns = g_sums[1], np = g_sums[2];
        double loss = (np == 0.0) ? (-ns / (double)totf)
                                  : (-(ps + ns) / (double)totf);
        out[0] = (float)loss;
    }
}

extern "C" void kernel_launch(void* const* d_in, const int* in_sizes, int n_in,
                              void* d_out, int out_size) {
    const float* pred   = (const float*)d_in[0];
    const float* target = (const float*)d_in[1];
    int npred = in_sizes[0];
    if (n_in >= 2 && in_sizes[1] < npred) {  // pred is the smaller tensor
        pred   = (const float*)d_in[1];
        target = (const float*)d_in[0];
        npred  = in_sizes[1];
    }
    int nvec = npred >> 2;

    const int blocks = 1184;   // 148 SMs * 8
    const int threads = 256;

    ghm_init<<<1, 32>>>();
    ghm_hist<<<blocks, threads>>>(pred, target, nvec);
    ghm_weights<<<1, 32>>>();
    ghm_loss<<<blocks, threads>>>(pred, target, nvec);
    ghm_final<<<1, 32>>>((float*)d_out);
}